// round 7
// baseline (speedup 1.0000x reference)
#include <cuda_runtime.h>
#include <cuda_bf16.h>
#include <math_constants.h>
#include <cstdint>

#define NN 50000
#define EE 800000
#define FDIM 256        // layer-1 feature dim (4 heads * 64)
#define F2DIM 40        // layer-2 feature dim (1 head * 40)
#define NEG_SLOPE 0.2f
#define SCAN_B 512
#define NBLK ((NN + SCAN_B - 1) / SCAN_B)   // 98

// ---------------- scratch (static device globals; no runtime allocation) ----
__device__ __align__(16) float g_feat1[NN * FDIM];   // x @ W1 ; front reused for feat2
__device__ __align__(16) float g_h2[NN * FDIM];      // elu(layer-1 out), flattened
__device__ int g_colidx[EE];
__device__ int g_counts[NN];
__device__ int g_rowptr[NN + 1];
__device__ int g_cursor[NN];
__device__ int g_bsum[NBLK];
#define G_FEAT2 g_feat1   // feat2[N,40] aliases g_feat1 (dead after agg1)

// ---------------- CSR build ------------------------------------------------
__global__ void zero_counts_kernel() {
    int i = blockIdx.x * blockDim.x + threadIdx.x;
    if (i < NN) g_counts[i] = 0;
}

__global__ void hist_kernel(const int* __restrict__ dst) {
    int e = blockIdx.x * blockDim.x + threadIdx.x;
    if (e < EE) atomicAdd(&g_counts[dst[e]], 1);
}

// phase A: per-block exclusive scan (local) + block sums
__global__ __launch_bounds__(SCAN_B) void scanA_kernel() {
    __shared__ int sh[SCAN_B];
    int i = blockIdx.x * SCAN_B + threadIdx.x;
    int v = (i < NN) ? g_counts[i] : 0;
    sh[threadIdx.x] = v;
    __syncthreads();
    #pragma unroll
    for (int off = 1; off < SCAN_B; off <<= 1) {
        int t = (threadIdx.x >= off) ? sh[threadIdx.x - off] : 0;
        __syncthreads();
        sh[threadIdx.x] += t;
        __syncthreads();
    }
    if (i < NN) g_rowptr[i] = sh[threadIdx.x] - v;       // local exclusive
    if (threadIdx.x == SCAN_B - 1) g_bsum[blockIdx.x] = sh[SCAN_B - 1];
}

// phase B: warp-shuffle exclusive scan of NBLK (=98) block sums, one block
__global__ __launch_bounds__(128) void scanB_kernel() {
    __shared__ int wsum[4];
    int t = threadIdx.x;
    int lane = t & 31, wid = t >> 5;
    int v = (t < NBLK) ? g_bsum[t] : 0;
    int x = v;
    #pragma unroll
    for (int off = 1; off < 32; off <<= 1) {
        int y = __shfl_up_sync(0xffffffffu, x, off);
        if (lane >= off) x += y;
    }
    if (lane == 31) wsum[wid] = x;
    __syncthreads();
    int add = 0;
    #pragma unroll
    for (int wq = 0; wq < 4; wq++) if (wq < wid) add += wsum[wq];
    if (t < NBLK) g_bsum[t] = x + add - v;   // exclusive
}

// phase C: add block offsets
__global__ void scanC_kernel() {
    int i = blockIdx.x * blockDim.x + threadIdx.x;
    if (i < NN) {
        int r = g_rowptr[i] + g_bsum[i / SCAN_B];
        g_rowptr[i] = r;
        g_cursor[i] = r;
    }
    if (i == 0) g_rowptr[NN] = EE;
}

__global__ void fill_kernel(const int* __restrict__ src, const int* __restrict__ dst) {
    int e = blockIdx.x * blockDim.x + threadIdx.x;
    if (e < EE) {
        int p = atomicAdd(&g_cursor[dst[e]], 1);
        g_colidx[p] = src[e];
    }
}

// ---------------- GEMM1 (tensor cores, tf32 2-term split, pre-split SMEM) ---
// feat1[N,256] = x[N,256] @ W1[256,256]
// block 128x128, BK=16, 8 warps (2 M x 4 N), warp tile 64x32, mma m16n8k8.
// (hi,lo) tf32 pair packed per element in SMEM -> mainloop is LDS.64 + MMA only.
__device__ __forceinline__ uint2 tf32pack(float x) {
    uint2 p;
    asm("cvt.rna.tf32.f32 %0, %1;" : "=r"(p.x) : "f"(x));
    float r = x - __uint_as_float(p.x);
    asm("cvt.rna.tf32.f32 %0, %1;" : "=r"(p.y) : "f"(r));
    return p;
}

__device__ __forceinline__ void mma_tf32(float* c, const uint32_t* a, const uint32_t* b) {
    asm volatile(
        "mma.sync.aligned.m16n8k8.row.col.f32.tf32.tf32.f32 "
        "{%0,%1,%2,%3}, {%4,%5,%6,%7}, {%8,%9}, {%0,%1,%2,%3};"
        : "+f"(c[0]), "+f"(c[1]), "+f"(c[2]), "+f"(c[3])
        : "r"(a[0]), "r"(a[1]), "r"(a[2]), "r"(a[3]), "r"(b[0]), "r"(b[1]));
}

__global__ __launch_bounds__(256) void gemm1_tc_kernel(const float* __restrict__ A,
                                                       const float* __restrict__ B) {
    __shared__ uint2 AsT[16][132];   // [k][m] (hi,lo) packed; pad 132
    __shared__ uint2 BsT[16][132];   // [k][n]
    int tid = threadIdx.x;
    int lane = tid & 31, wid = tid >> 5;
    int g = lane >> 2, t4 = lane & 3;
    int row0 = blockIdx.x * 128, col0 = blockIdx.y * 128;
    int wm = (wid & 1) * 64, wn = (wid >> 1) * 32;

    float c[4][4][4];
    #pragma unroll
    for (int mt = 0; mt < 4; mt++)
        #pragma unroll
        for (int nt = 0; nt < 4; nt++)
            #pragma unroll
            for (int q = 0; q < 4; q++) c[mt][nt][q] = 0.f;

    int am = tid >> 1;              // 0..127  (A row within tile)
    int ak = (tid & 1) * 8;         // A k-offset: 0 or 8
    int bk = tid >> 4;              // 0..15    (B k-row)
    int bn = (tid & 15) * 8;        // 0..120   (B col)

    for (int k0 = 0; k0 < FDIM; k0 += 16) {
        // A tile -> AsT[k][m] transposed, split once per element
        {
            int r = row0 + am;
            float4 v0 = make_float4(0.f, 0.f, 0.f, 0.f);
            float4 v1 = make_float4(0.f, 0.f, 0.f, 0.f);
            if (r < NN) {
                v0 = *(const float4*)&A[(size_t)r * FDIM + k0 + ak];
                v1 = *(const float4*)&A[(size_t)r * FDIM + k0 + ak + 4];
            }
            AsT[ak + 0][am] = tf32pack(v0.x);
            AsT[ak + 1][am] = tf32pack(v0.y);
            AsT[ak + 2][am] = tf32pack(v0.z);
            AsT[ak + 3][am] = tf32pack(v0.w);
            AsT[ak + 4][am] = tf32pack(v1.x);
            AsT[ak + 5][am] = tf32pack(v1.y);
            AsT[ak + 6][am] = tf32pack(v1.z);
            AsT[ak + 7][am] = tf32pack(v1.w);
        }
        // B tile -> BsT[k][n]
        {
            float4 v0 = *(const float4*)&B[(size_t)(k0 + bk) * 256 + col0 + bn];
            float4 v1 = *(const float4*)&B[(size_t)(k0 + bk) * 256 + col0 + bn + 4];
            BsT[bk][bn + 0] = tf32pack(v0.x);
            BsT[bk][bn + 1] = tf32pack(v0.y);
            BsT[bk][bn + 2] = tf32pack(v0.z);
            BsT[bk][bn + 3] = tf32pack(v0.w);
            BsT[bk][bn + 4] = tf32pack(v1.x);
            BsT[bk][bn + 5] = tf32pack(v1.y);
            BsT[bk][bn + 6] = tf32pack(v1.z);
            BsT[bk][bn + 7] = tf32pack(v1.w);
        }
        __syncthreads();

        #pragma unroll
        for (int ks = 0; ks < 2; ks++) {
            int kb = ks * 8;
            uint32_t ahi[4][4], alo[4][4];
            #pragma unroll
            for (int mt = 0; mt < 4; mt++) {
                int mr = wm + mt * 16;
                uint2 a0 = AsT[kb + t4][mr + g];
                uint2 a1 = AsT[kb + t4][mr + g + 8];
                uint2 a2 = AsT[kb + t4 + 4][mr + g];
                uint2 a3 = AsT[kb + t4 + 4][mr + g + 8];
                ahi[mt][0] = a0.x; alo[mt][0] = a0.y;
                ahi[mt][1] = a1.x; alo[mt][1] = a1.y;
                ahi[mt][2] = a2.x; alo[mt][2] = a2.y;
                ahi[mt][3] = a3.x; alo[mt][3] = a3.y;
            }
            uint32_t bhi[4][2], blo[4][2];
            #pragma unroll
            for (int nt = 0; nt < 4; nt++) {
                int nc = wn + nt * 8 + g;
                uint2 b0 = BsT[kb + t4][nc];
                uint2 b1 = BsT[kb + t4 + 4][nc];
                bhi[nt][0] = b0.x; blo[nt][0] = b0.y;
                bhi[nt][1] = b1.x; blo[nt][1] = b1.y;
            }
            #pragma unroll
            for (int mt = 0; mt < 4; mt++)
                #pragma unroll
                for (int nt = 0; nt < 4; nt++) {
                    mma_tf32(c[mt][nt], ahi[mt], bhi[nt]);
                    mma_tf32(c[mt][nt], ahi[mt], blo[nt]);
                    mma_tf32(c[mt][nt], alo[mt], bhi[nt]);
                }
        }
        __syncthreads();
    }

    // epilogue: c0,c1 -> (row g, cols 2t4,2t4+1); c2,c3 -> row g+8
    #pragma unroll
    for (int mt = 0; mt < 4; mt++) {
        int r = row0 + wm + mt * 16 + g;
        #pragma unroll
        for (int nt = 0; nt < 4; nt++) {
            int cc = col0 + wn + nt * 8 + 2 * t4;
            if (r < NN)
                *(float2*)&g_feat1[(size_t)r * FDIM + cc] = make_float2(c[mt][nt][0], c[mt][nt][1]);
            if (r + 8 < NN)
                *(float2*)&g_feat1[(size_t)(r + 8) * FDIM + cc] = make_float2(c[mt][nt][2], c[mt][nt][3]);
        }
    }
}

// ---------------- layer-1 fused edge-softmax + aggregate --------------------
__device__ __forceinline__ float4 leaky4(float4 v) {
    float4 r;
    r.x = v.x > 0.f ? v.x : NEG_SLOPE * v.x;
    r.y = v.y > 0.f ? v.y : NEG_SLOPE * v.y;
    r.z = v.z > 0.f ? v.z : NEG_SLOPE * v.z;
    r.w = v.w > 0.f ? v.w : NEG_SLOPE * v.w;
    return r;
}
__device__ __forceinline__ float eluf(float x) { return x > 0.f ? x : expm1f(x); }

__device__ __forceinline__ float dot4(float4 a, float4 b) {
    return a.x * b.x + a.y * b.y + a.z * b.z + a.w * b.w;
}
__device__ __forceinline__ float4 add4(float4 a, float4 b) {
    return make_float4(a.x + b.x, a.y + b.y, a.z + b.z, a.w + b.w);
}

__global__ __launch_bounds__(256) void agg1_kernel(const float* __restrict__ attn) {
    int w = (blockIdx.x * blockDim.x + threadIdx.x) >> 5;   // always < NN by grid sizing
    int lane = threadIdx.x & 31;

    const float4* feat = (const float4*)g_feat1;   // 64 float4 per row
    const float4* at4  = (const float4*)attn;

    float4 aA = at4[lane];
    float4 aB = at4[32 + lane];
    float4 fd0 = feat[(size_t)w * 64 + lane];
    float4 fd1 = feat[(size_t)w * 64 + 32 + lane];

    int beg = g_rowptr[w], end = g_rowptr[w + 1];
    float mA = -CUDART_INF_F, mB = -CUDART_INF_F, dA = 0.f, dB = 0.f;
    float4 acc0 = make_float4(0.f, 0.f, 0.f, 0.f);
    float4 acc1 = make_float4(0.f, 0.f, 0.f, 0.f);

    int k = beg;
    for (; k + 1 < end; k += 2) {
        int sa = g_colidx[k];
        int sb = g_colidx[k + 1];
        float4 va0 = feat[(size_t)sa * 64 + lane];
        float4 va1 = feat[(size_t)sa * 64 + 32 + lane];
        float4 vb0 = feat[(size_t)sb * 64 + lane];
        float4 vb1 = feat[(size_t)sb * 64 + 32 + lane];
        float pa0 = dot4(leaky4(add4(va0, fd0)), aA);
        float pa1 = dot4(leaky4(add4(va1, fd1)), aB);
        float pb0 = dot4(leaky4(add4(vb0, fd0)), aA);
        float pb1 = dot4(leaky4(add4(vb1, fd1)), aB);
        #pragma unroll
        for (int off = 8; off > 0; off >>= 1) {
            pa0 += __shfl_xor_sync(0xffffffffu, pa0, off);
            pa1 += __shfl_xor_sync(0xffffffffu, pa1, off);
            pb0 += __shfl_xor_sync(0xffffffffu, pb0, off);
            pb1 += __shfl_xor_sync(0xffffffffu, pb1, off);
        }
        {
            float nmA = fmaxf(mA, pa0), nmB = fmaxf(mB, pa1);
            float scA = __expf(mA - nmA), exA = __expf(pa0 - nmA);
            float scB = __expf(mB - nmB), exB = __expf(pa1 - nmB);
            dA = dA * scA + exA;
            dB = dB * scB + exB;
            acc0.x = acc0.x * scA + exA * va0.x; acc0.y = acc0.y * scA + exA * va0.y;
            acc0.z = acc0.z * scA + exA * va0.z; acc0.w = acc0.w * scA + exA * va0.w;
            acc1.x = acc1.x * scB + exB * va1.x; acc1.y = acc1.y * scB + exB * va1.y;
            acc1.z = acc1.z * scB + exB * va1.z; acc1.w = acc1.w * scB + exB * va1.w;
            mA = nmA; mB = nmB;
        }
        {
            float nmA = fmaxf(mA, pb0), nmB = fmaxf(mB, pb1);
            float scA = __expf(mA - nmA), exA = __expf(pb0 - nmA);
            float scB = __expf(mB - nmB), exB = __expf(pb1 - nmB);
            dA = dA * scA + exA;
            dB = dB * scB + exB;
            acc0.x = acc0.x * scA + exA * vb0.x; acc0.y = acc0.y * scA + exA * vb0.y;
            acc0.z = acc0.z * scA + exA * vb0.z; acc0.w = acc0.w * scA + exA * vb0.w;
            acc1.x = acc1.x * scB + exB * vb1.x; acc1.y = acc1.y * scB + exB * vb1.y;
            acc1.z = acc1.z * scB + exB * vb1.z; acc1.w = acc1.w * scB + exB * vb1.w;
            mA = nmA; mB = nmB;
        }
    }
    if (k < end) {
        int s = g_colidx[k];
        float4 v0 = feat[(size_t)s * 64 + lane];
        float4 v1 = feat[(size_t)s * 64 + 32 + lane];
        float p0 = dot4(leaky4(add4(v0, fd0)), aA);
        float p1 = dot4(leaky4(add4(v1, fd1)), aB);
        #pragma unroll
        for (int off = 8; off > 0; off >>= 1) {
            p0 += __shfl_xor_sync(0xffffffffu, p0, off);
            p1 += __shfl_xor_sync(0xffffffffu, p1, off);
        }
        float nmA = fmaxf(mA, p0), nmB = fmaxf(mB, p1);
        float scA = __expf(mA - nmA), exA = __expf(p0 - nmA);
        float scB = __expf(mB - nmB), exB = __expf(p1 - nmB);
        dA = dA * scA + exA;
        dB = dB * scB + exB;
        acc0.x = acc0.x * scA + exA * v0.x; acc0.y = acc0.y * scA + exA * v0.y;
        acc0.z = acc0.z * scA + exA * v0.z; acc0.w = acc0.w * scA + exA * v0.w;
        acc1.x = acc1.x * scB + exB * v1.x; acc1.y = acc1.y * scB + exB * v1.y;
        acc1.z = acc1.z * scB + exB * v1.z; acc1.w = acc1.w * scB + exB * v1.w;
    }

    float iA = dA > 0.f ? 1.f / dA : 0.f;
    float iB = dB > 0.f ? 1.f / dB : 0.f;
    float4 o0 = make_float4(eluf(acc0.x * iA), eluf(acc0.y * iA), eluf(acc0.z * iA), eluf(acc0.w * iA));
    float4 o1 = make_float4(eluf(acc1.x * iB), eluf(acc1.y * iB), eluf(acc1.z * iB), eluf(acc1.w * iB));
    float4* out = (float4*)g_h2;
    out[(size_t)w * 64 + lane] = o0;
    out[(size_t)w * 64 + 32 + lane] = o1;
}

// ---------------- GEMM2: feat2[N,40] = h2[N,256] @ W2[256,40] ---------------
__global__ __launch_bounds__(256) void gemm2_kernel(const float* __restrict__ W2) {
    __shared__ float hs[4][256];
    int n0 = blockIdx.x * 4;
    int tid = threadIdx.y * 64 + threadIdx.x;
    for (int i = tid; i < 1024; i += 256) {
        int r = n0 + (i >> 8);
        hs[i >> 8][i & 255] = (r < NN) ? g_h2[(size_t)r * 256 + (i & 255)] : 0.f;
    }
    __syncthreads();
    int c = threadIdx.x;
    int r = n0 + threadIdx.y;
    if (c < F2DIM && r < NN) {
        float s = 0.f;
        #pragma unroll 8
        for (int k = 0; k < 256; k++) s += hs[threadIdx.y][k] * W2[k * F2DIM + c];
        G_FEAT2[(size_t)r * F2DIM + c] = s;
    }
}

// ---------------- layer-2 fused edge-softmax + aggregate --------------------
__global__ __launch_bounds__(256) void agg2_kernel(const float* __restrict__ attn2,
                                                   float* __restrict__ out) {
    int w = (blockIdx.x * blockDim.x + threadIdx.x) >> 5;
    int lane = threadIdx.x & 31;

    bool hi = lane < 8;
    float a_lo = attn2[lane];
    float a_hi = hi ? attn2[32 + lane] : 0.f;
    float fd_lo = G_FEAT2[(size_t)w * F2DIM + lane];
    float fd_hi = hi ? G_FEAT2[(size_t)w * F2DIM + 32 + lane] : 0.f;

    int beg = g_rowptr[w], end = g_rowptr[w + 1];
    float m = -CUDART_INF_F, d = 0.f, acc_lo = 0.f, acc_hi = 0.f;

    for (int k = beg; k < end; k++) {
        int s = g_colidx[k];
        float v_lo = G_FEAT2[(size_t)s * F2DIM + lane];
        float v_hi = hi ? G_FEAT2[(size_t)s * F2DIM + 32 + lane] : 0.f;
        float e_lo = v_lo + fd_lo; e_lo = e_lo > 0.f ? e_lo : NEG_SLOPE * e_lo;
        float e_hi = v_hi + fd_hi; e_hi = e_hi > 0.f ? e_hi : NEG_SLOPE * e_hi;
        float p = e_lo * a_lo + e_hi * a_hi;
        #pragma unroll
        for (int off = 16; off > 0; off >>= 1) p += __shfl_xor_sync(0xffffffffu, p, off);
        float nm = fmaxf(m, p);
        float sc = __expf(m - nm);
        float ex = __expf(p - nm);
        d = d * sc + ex;
        acc_lo = acc_lo * sc + ex * v_lo;
        acc_hi = acc_hi * sc + ex * v_hi;
        m = nm;
    }

    float inv = d > 0.f ? 1.f / d : 0.f;
    out[(size_t)w * F2DIM + lane] = acc_lo * inv;
    if (hi) out[(size_t)w * F2DIM + 32 + lane] = acc_hi * inv;
}

// ---------------- launch ----------------------------------------------------
extern "C" void kernel_launch(void* const* d_in, const int* in_sizes, int n_in,
                              void* d_out, int out_size) {
    const float* x     = (const float*)d_in[0];
    const int*   src   = (const int*)d_in[1];
    const int*   dst   = (const int*)d_in[2];
    const float* W1    = (const float*)d_in[3];
    const float* attn1 = (const float*)d_in[4];
    const float* W2    = (const float*)d_in[5];
    const float* attn2 = (const float*)d_in[6];
    float* out = (float*)d_out;

    // CSR by destination
    zero_counts_kernel<<<(NN + 255) / 256, 256>>>();
    hist_kernel<<<(EE + 255) / 256, 256>>>(dst);
    scanA_kernel<<<NBLK, SCAN_B>>>();
    scanB_kernel<<<1, 128>>>();
    scanC_kernel<<<(NN + 255) / 256, 256>>>();
    fill_kernel<<<(EE + 255) / 256, 256>>>(src, dst);

    // layer 1
    gemm1_tc_kernel<<<dim3((NN + 127) / 128, 2), 256>>>(x, W1);
    agg1_kernel<<<(NN * 32) / 256, 256>>>(attn1);

    // layer 2
    gemm2_kernel<<<(NN + 3) / 4, dim3(64, 4)>>>(W2);
    agg2_kernel<<<(NN * 32) / 256, 256>>>(attn2, out);
}

// round 8
// speedup vs baseline: 1.1788x; 1.1788x over previous
#include <cuda_runtime.h>
#include <cuda_bf16.h>
#include <math_constants.h>
#include <cstdint>

#define NN 50000
#define EE 800000
#define FDIM 256        // layer-1 feature dim (4 heads * 64)
#define F2DIM 40        // layer-2 feature dim (1 head * 40)
#define NEG_SLOPE 0.2f
#define SCAN_B 512
#define NBLK ((NN + SCAN_B - 1) / SCAN_B)   // 98

// ---------------- scratch (static device globals; no runtime allocation) ----
__device__ __align__(16) float g_feat1[NN * FDIM];   // x @ W1 (PERMUTED cols); front reused for feat2
__device__ __align__(16) float g_h2[NN * FDIM];      // elu(layer-1 out), PERMUTED cols
__device__ int g_colidx[EE];
__device__ int g_counts[NN];
__device__ int g_rowptr[NN + 1];
__device__ int g_cursor[NN];
__device__ int g_bsum[NBLK];
#define G_FEAT2 g_feat1   // feat2[N,40] aliases g_feat1 (dead after agg1)

// Column permutation: head-local lane ownership for agg1.
// orig col c -> group go=c>>2 (head h=go>>4, j=go&15); slot s = j<8 ? 8h+j : 32+8h+(j-8).
__device__ __forceinline__ int permcol(int c) {
    int go = c >> 2, q = c & 3;
    int h = go >> 4, j = go & 15;
    int s = (j < 8) ? (8 * h + j) : (32 + 8 * h + (j - 8));
    return s * 4 + q;
}
__device__ __forceinline__ int invcol(int c) {
    int s = c >> 2, q = c & 3;
    int go;
    if (s < 32) go = 16 * (s >> 3) + (s & 7);
    else { int t = s - 32; go = 16 * (t >> 3) + 8 + (t & 7); }
    return go * 4 + q;
}

// ---------------- CSR build ------------------------------------------------
__global__ void zero_counts_kernel() {
    int i = blockIdx.x * blockDim.x + threadIdx.x;
    if (i < NN) g_counts[i] = 0;
}

__global__ void hist_kernel(const int* __restrict__ dst) {
    int e = blockIdx.x * blockDim.x + threadIdx.x;
    if (e < EE) atomicAdd(&g_counts[dst[e]], 1);
}

__global__ __launch_bounds__(SCAN_B) void scanA_kernel() {
    __shared__ int sh[SCAN_B];
    int i = blockIdx.x * SCAN_B + threadIdx.x;
    int v = (i < NN) ? g_counts[i] : 0;
    sh[threadIdx.x] = v;
    __syncthreads();
    #pragma unroll
    for (int off = 1; off < SCAN_B; off <<= 1) {
        int t = (threadIdx.x >= off) ? sh[threadIdx.x - off] : 0;
        __syncthreads();
        sh[threadIdx.x] += t;
        __syncthreads();
    }
    if (i < NN) g_rowptr[i] = sh[threadIdx.x] - v;
    if (threadIdx.x == SCAN_B - 1) g_bsum[blockIdx.x] = sh[SCAN_B - 1];
}

__global__ __launch_bounds__(128) void scanB_kernel() {
    __shared__ int wsum[4];
    int t = threadIdx.x;
    int lane = t & 31, wid = t >> 5;
    int v = (t < NBLK) ? g_bsum[t] : 0;
    int x = v;
    #pragma unroll
    for (int off = 1; off < 32; off <<= 1) {
        int y = __shfl_up_sync(0xffffffffu, x, off);
        if (lane >= off) x += y;
    }
    if (lane == 31) wsum[wid] = x;
    __syncthreads();
    int add = 0;
    #pragma unroll
    for (int wq = 0; wq < 4; wq++) if (wq < wid) add += wsum[wq];
    if (t < NBLK) g_bsum[t] = x + add - v;
}

__global__ void scanC_kernel() {
    int i = blockIdx.x * blockDim.x + threadIdx.x;
    if (i < NN) {
        int r = g_rowptr[i] + g_bsum[i / SCAN_B];
        g_rowptr[i] = r;
        g_cursor[i] = r;
    }
    if (i == 0) g_rowptr[NN] = EE;
}

__global__ void fill_kernel(const int* __restrict__ src, const int* __restrict__ dst) {
    int e = blockIdx.x * blockDim.x + threadIdx.x;
    if (e < EE) {
        int p = atomicAdd(&g_cursor[dst[e]], 1);
        g_colidx[p] = src[e];
    }
}

// ---------------- GEMM1 (R5 version: BK=32, in-loop tf32 split) -------------
__device__ __forceinline__ void tf32split(float x, uint32_t& hi, uint32_t& lo) {
    asm("cvt.rna.tf32.f32 %0, %1;" : "=r"(hi) : "f"(x));
    float r = x - __uint_as_float(hi);
    asm("cvt.rna.tf32.f32 %0, %1;" : "=r"(lo) : "f"(r));
}

__device__ __forceinline__ void mma_tf32(float* c, const uint32_t* a, const uint32_t* b) {
    asm volatile(
        "mma.sync.aligned.m16n8k8.row.col.f32.tf32.tf32.f32 "
        "{%0,%1,%2,%3}, {%4,%5,%6,%7}, {%8,%9}, {%0,%1,%2,%3};"
        : "+f"(c[0]), "+f"(c[1]), "+f"(c[2]), "+f"(c[3])
        : "r"(a[0]), "r"(a[1]), "r"(a[2]), "r"(a[3]), "r"(b[0]), "r"(b[1]));
}

__global__ __launch_bounds__(256) void gemm1_tc_kernel(const float* __restrict__ A,
                                                       const float* __restrict__ B) {
    __shared__ float As[32][136];
    __shared__ float Bs[32][136];
    int tid = threadIdx.x;
    int lane = tid & 31, wid = tid >> 5;
    int g = lane >> 2, t4 = lane & 3;
    int row0 = blockIdx.x * 128, col0 = blockIdx.y * 128;
    int wm = (wid & 1) * 64, wn = (wid >> 1) * 32;

    float c[4][4][4];
    #pragma unroll
    for (int mt = 0; mt < 4; mt++)
        #pragma unroll
        for (int nt = 0; nt < 4; nt++)
            #pragma unroll
            for (int q = 0; q < 4; q++) c[mt][nt][q] = 0.f;

    int am = tid >> 1;
    int akh = (tid & 1) * 16;
    int bkr = tid >> 5;
    int bnc = lane * 4;

    for (int k0 = 0; k0 < FDIM; k0 += 32) {
        #pragma unroll
        for (int q = 0; q < 4; q++) {
            int kk = akh + q * 4;
            float4 v = make_float4(0.f, 0.f, 0.f, 0.f);
            int r = row0 + am;
            if (r < NN) v = *(const float4*)&A[(size_t)r * FDIM + k0 + kk];
            As[kk + 0][am] = v.x;
            As[kk + 1][am] = v.y;
            As[kk + 2][am] = v.z;
            As[kk + 3][am] = v.w;
        }
        #pragma unroll
        for (int q = 0; q < 4; q++) {
            float4 v = *(const float4*)&B[(size_t)(k0 + bkr + q * 8) * 256 + col0 + bnc];
            *(float4*)&Bs[bkr + q * 8][bnc] = v;
        }
        __syncthreads();

        #pragma unroll
        for (int ks = 0; ks < 4; ks++) {
            int kb = ks * 8;
            uint32_t ahi[4][4], alo[4][4];
            #pragma unroll
            for (int mt = 0; mt < 4; mt++) {
                int mr = wm + mt * 16;
                float a0 = As[kb + t4][mr + g];
                float a1 = As[kb + t4][mr + g + 8];
                float a2 = As[kb + t4 + 4][mr + g];
                float a3 = As[kb + t4 + 4][mr + g + 8];
                tf32split(a0, ahi[mt][0], alo[mt][0]);
                tf32split(a1, ahi[mt][1], alo[mt][1]);
                tf32split(a2, ahi[mt][2], alo[mt][2]);
                tf32split(a3, ahi[mt][3], alo[mt][3]);
            }
            uint32_t bhi[4][2], blo[4][2];
            #pragma unroll
            for (int nt = 0; nt < 4; nt++) {
                int nc = wn + nt * 8 + g;
                float b0 = Bs[kb + t4][nc];
                float b1 = Bs[kb + t4 + 4][nc];
                tf32split(b0, bhi[nt][0], blo[nt][0]);
                tf32split(b1, bhi[nt][1], blo[nt][1]);
            }
            #pragma unroll
            for (int mt = 0; mt < 4; mt++)
                #pragma unroll
                for (int nt = 0; nt < 4; nt++) {
                    mma_tf32(c[mt][nt], ahi[mt], bhi[nt]);
                    mma_tf32(c[mt][nt], ahi[mt], blo[nt]);
                    mma_tf32(c[mt][nt], alo[mt], bhi[nt]);
                }
        }
        __syncthreads();
    }

    // epilogue: write PERMUTED columns (float2 stays within one float4 group)
    #pragma unroll
    for (int mt = 0; mt < 4; mt++) {
        int r = row0 + wm + mt * 16 + g;
        #pragma unroll
        for (int nt = 0; nt < 4; nt++) {
            int cc = col0 + wn + nt * 8 + 2 * t4;
            int nc = permcol(cc);
            if (r < NN)
                *(float2*)&g_feat1[(size_t)r * FDIM + nc] = make_float2(c[mt][nt][0], c[mt][nt][1]);
            if (r + 8 < NN)
                *(float2*)&g_feat1[(size_t)(r + 8) * FDIM + nc] = make_float2(c[mt][nt][2], c[mt][nt][3]);
        }
    }
}

// ---------------- layer-1 fused edge-softmax + aggregate --------------------
// Permuted layout: lane l owns 8 dims of head (l>>3) via float4 slots l and 32+l.
// Score reduce = ONE 3-stage shuffle within 8-lane groups; ONE softmax chain.
__device__ __forceinline__ float4 leaky4(float4 v) {
    float4 r;
    r.x = v.x > 0.f ? v.x : NEG_SLOPE * v.x;
    r.y = v.y > 0.f ? v.y : NEG_SLOPE * v.y;
    r.z = v.z > 0.f ? v.z : NEG_SLOPE * v.z;
    r.w = v.w > 0.f ? v.w : NEG_SLOPE * v.w;
    return r;
}
__device__ __forceinline__ float eluf(float x) { return x > 0.f ? x : expm1f(x); }
__device__ __forceinline__ float dot4(float4 a, float4 b) {
    return a.x * b.x + a.y * b.y + a.z * b.z + a.w * b.w;
}
__device__ __forceinline__ float4 add4(float4 a, float4 b) {
    return make_float4(a.x + b.x, a.y + b.y, a.z + b.z, a.w + b.w);
}

__global__ __launch_bounds__(256) void agg1_kernel(const float* __restrict__ attn) {
    int w = (blockIdx.x * blockDim.x + threadIdx.x) >> 5;   // < NN by grid sizing
    int lane = threadIdx.x & 31;

    const float4* feat = (const float4*)g_feat1;   // permuted, 64 float4/row
    const float4* at4  = (const float4*)attn;      // orig layout

    // attn groups for this lane's slots (orig indices)
    int hh = lane >> 3, jj = lane & 7;
    float4 aA = at4[16 * hh + jj];
    float4 aB = at4[16 * hh + 8 + jj];
    float4 fd0 = feat[(size_t)w * 64 + lane];
    float4 fd1 = feat[(size_t)w * 64 + 32 + lane];

    int beg = g_rowptr[w], end = g_rowptr[w + 1];
    float m = -CUDART_INF_F, d = 0.f;
    float4 acc0 = make_float4(0.f, 0.f, 0.f, 0.f);
    float4 acc1 = make_float4(0.f, 0.f, 0.f, 0.f);

    int k = beg;
    for (; k + 1 < end; k += 2) {
        int sa = g_colidx[k];
        int sb = g_colidx[k + 1];
        float4 va0 = feat[(size_t)sa * 64 + lane];
        float4 va1 = feat[(size_t)sa * 64 + 32 + lane];
        float4 vb0 = feat[(size_t)sb * 64 + lane];
        float4 vb1 = feat[(size_t)sb * 64 + 32 + lane];
        float pa = dot4(leaky4(add4(va0, fd0)), aA) + dot4(leaky4(add4(va1, fd1)), aB);
        float pb = dot4(leaky4(add4(vb0, fd0)), aA) + dot4(leaky4(add4(vb1, fd1)), aB);
        #pragma unroll
        for (int off = 4; off > 0; off >>= 1) {
            pa += __shfl_xor_sync(0xffffffffu, pa, off);
            pb += __shfl_xor_sync(0xffffffffu, pb, off);
        }
        {
            float nm = fmaxf(m, pa);
            float sc = __expf(m - nm);
            float ex = __expf(pa - nm);
            d = d * sc + ex;
            acc0.x = acc0.x * sc + ex * va0.x; acc0.y = acc0.y * sc + ex * va0.y;
            acc0.z = acc0.z * sc + ex * va0.z; acc0.w = acc0.w * sc + ex * va0.w;
            acc1.x = acc1.x * sc + ex * va1.x; acc1.y = acc1.y * sc + ex * va1.y;
            acc1.z = acc1.z * sc + ex * va1.z; acc1.w = acc1.w * sc + ex * va1.w;
            m = nm;
        }
        {
            float nm = fmaxf(m, pb);
            float sc = __expf(m - nm);
            float ex = __expf(pb - nm);
            d = d * sc + ex;
            acc0.x = acc0.x * sc + ex * vb0.x; acc0.y = acc0.y * sc + ex * vb0.y;
            acc0.z = acc0.z * sc + ex * vb0.z; acc0.w = acc0.w * sc + ex * vb0.w;
            acc1.x = acc1.x * sc + ex * vb1.x; acc1.y = acc1.y * sc + ex * vb1.y;
            acc1.z = acc1.z * sc + ex * vb1.z; acc1.w = acc1.w * sc + ex * vb1.w;
            m = nm;
        }
    }
    if (k < end) {
        int s = g_colidx[k];
        float4 v0 = feat[(size_t)s * 64 + lane];
        float4 v1 = feat[(size_t)s * 64 + 32 + lane];
        float p = dot4(leaky4(add4(v0, fd0)), aA) + dot4(leaky4(add4(v1, fd1)), aB);
        #pragma unroll
        for (int off = 4; off > 0; off >>= 1) p += __shfl_xor_sync(0xffffffffu, p, off);
        float nm = fmaxf(m, p);
        float sc = __expf(m - nm);
        float ex = __expf(p - nm);
        d = d * sc + ex;
        acc0.x = acc0.x * sc + ex * v0.x; acc0.y = acc0.y * sc + ex * v0.y;
        acc0.z = acc0.z * sc + ex * v0.z; acc0.w = acc0.w * sc + ex * v0.w;
        acc1.x = acc1.x * sc + ex * v1.x; acc1.y = acc1.y * sc + ex * v1.y;
        acc1.z = acc1.z * sc + ex * v1.z; acc1.w = acc1.w * sc + ex * v1.w;
    }

    float inv = d > 0.f ? 1.f / d : 0.f;
    float4 o0 = make_float4(eluf(acc0.x * inv), eluf(acc0.y * inv), eluf(acc0.z * inv), eluf(acc0.w * inv));
    float4 o1 = make_float4(eluf(acc1.x * inv), eluf(acc1.y * inv), eluf(acc1.z * inv), eluf(acc1.w * inv));
    float4* out = (float4*)g_h2;                    // permuted layout
    out[(size_t)w * 64 + lane] = o0;
    out[(size_t)w * 64 + 32 + lane] = o1;
}

// ---------------- GEMM2: feat2[N,40] = h2[N,256] @ W2[256,40] ---------------
// h2 is in permuted layout; unpermute into SMEM (coalesced global, scattered STS).
__global__ __launch_bounds__(256) void gemm2_kernel(const float* __restrict__ W2) {
    __shared__ float hs[4][256];
    int n0 = blockIdx.x * 4;
    int tid = threadIdx.y * 64 + threadIdx.x;
    for (int i = tid; i < 1024; i += 256) {
        int r = n0 + (i >> 8);
        int pc = i & 255;                           // permuted col (contiguous load)
        float v = (r < NN) ? g_h2[(size_t)r * 256 + pc] : 0.f;
        hs[i >> 8][invcol(pc)] = v;                 // store at orig col
    }
    __syncthreads();
    int c = threadIdx.x;
    int r = n0 + threadIdx.y;
    if (c < F2DIM && r < NN) {
        float s = 0.f;
        #pragma unroll 8
        for (int k = 0; k < 256; k++) s += hs[threadIdx.y][k] * W2[k * F2DIM + c];
        G_FEAT2[(size_t)r * F2DIM + c] = s;
    }
}

// ---------------- layer-2 fused edge-softmax + aggregate --------------------
__global__ __launch_bounds__(256) void agg2_kernel(const float* __restrict__ attn2,
                                                   float* __restrict__ out) {
    int w = (blockIdx.x * blockDim.x + threadIdx.x) >> 5;
    int lane = threadIdx.x & 31;

    bool hi = lane < 8;
    float a_lo = attn2[lane];
    float a_hi = hi ? attn2[32 + lane] : 0.f;
    float fd_lo = G_FEAT2[(size_t)w * F2DIM + lane];
    float fd_hi = hi ? G_FEAT2[(size_t)w * F2DIM + 32 + lane] : 0.f;

    int beg = g_rowptr[w], end = g_rowptr[w + 1];
    float m = -CUDART_INF_F, d = 0.f, acc_lo = 0.f, acc_hi = 0.f;

    for (int k = beg; k < end; k++) {
        int s = g_colidx[k];
        float v_lo = G_FEAT2[(size_t)s * F2DIM + lane];
        float v_hi = hi ? G_FEAT2[(size_t)s * F2DIM + 32 + lane] : 0.f;
        float e_lo = v_lo + fd_lo; e_lo = e_lo > 0.f ? e_lo : NEG_SLOPE * e_lo;
        float e_hi = v_hi + fd_hi; e_hi = e_hi > 0.f ? e_hi : NEG_SLOPE * e_hi;
        float p = e_lo * a_lo + e_hi * a_hi;
        #pragma unroll
        for (int off = 16; off > 0; off >>= 1) p += __shfl_xor_sync(0xffffffffu, p, off);
        float nm = fmaxf(m, p);
        float sc = __expf(m - nm);
        float ex = __expf(p - nm);
        d = d * sc + ex;
        acc_lo = acc_lo * sc + ex * v_lo;
        acc_hi = acc_hi * sc + ex * v_hi;
        m = nm;
    }

    float inv = d > 0.f ? 1.f / d : 0.f;
    out[(size_t)w * F2DIM + lane] = acc_lo * inv;
    if (hi) out[(size_t)w * F2DIM + 32 + lane] = acc_hi * inv;
}

// ---------------- launch ----------------------------------------------------
extern "C" void kernel_launch(void* const* d_in, const int* in_sizes, int n_in,
                              void* d_out, int out_size) {
    const float* x     = (const float*)d_in[0];
    const int*   src   = (const int*)d_in[1];
    const int*   dst   = (const int*)d_in[2];
    const float* W1    = (const float*)d_in[3];
    const float* attn1 = (const float*)d_in[4];
    const float* W2    = (const float*)d_in[5];
    const float* attn2 = (const float*)d_in[6];
    float* out = (float*)d_out;

    zero_counts_kernel<<<(NN + 255) / 256, 256>>>();
    hist_kernel<<<(EE + 255) / 256, 256>>>(dst);
    scanA_kernel<<<NBLK, SCAN_B>>>();
    scanB_kernel<<<1, 128>>>();
    scanC_kernel<<<(NN + 255) / 256, 256>>>();
    fill_kernel<<<(EE + 255) / 256, 256>>>(src, dst);

    gemm1_tc_kernel<<<dim3((NN + 127) / 128, 2), 256>>>(x, W1);
    agg1_kernel<<<(NN * 32) / 256, 256>>>(attn1);

    gemm2_kernel<<<(NN + 3) / 4, dim3(64, 4)>>>(W2);
    agg2_kernel<<<(NN * 32) / 256, 256>>>(attn2, out);
}

// round 9
// speedup vs baseline: 1.2942x; 1.0979x over previous
#include <cuda_runtime.h>
#include <cuda_bf16.h>
#include <math_constants.h>
#include <cstdint>

#define NN 50000
#define EE 800000
#define FDIM 256        // layer-1 feature dim (4 heads * 64)
#define F2DIM 40        // layer-2 feature dim (1 head * 40)
#define NEG_SLOPE 0.2f
#define SCAN_B 512
#define NBLK ((NN + SCAN_B - 1) / SCAN_B)   // 98

// ---------------- scratch (static device globals; no runtime allocation) ----
__device__ __align__(16) float g_feat1[NN * FDIM];   // x @ W1 (PERMUTED cols); front reused for feat2
__device__ __align__(16) float g_h2[NN * FDIM];      // elu(layer-1 out), PERMUTED cols
__device__ int g_colidx[EE];
__device__ int g_counts[NN];
__device__ int g_rowptr[NN + 1];
__device__ int g_cursor[NN];
__device__ int g_bsum[NBLK];
#define G_FEAT2 g_feat1   // feat2[N,40] aliases g_feat1 (dead after agg1)

// Column permutation: head-local lane ownership for agg1.
__device__ __forceinline__ int permcol(int c) {
    int go = c >> 2, q = c & 3;
    int h = go >> 4, j = go & 15;
    int s = (j < 8) ? (8 * h + j) : (32 + 8 * h + (j - 8));
    return s * 4 + q;
}
__device__ __forceinline__ int invcol(int c) {
    int s = c >> 2, q = c & 3;
    int go;
    if (s < 32) go = 16 * (s >> 3) + (s & 7);
    else { int t = s - 32; go = 16 * (t >> 3) + 8 + (t & 7); }
    return go * 4 + q;
}

// ---------------- CSR build ------------------------------------------------
__global__ void zero_counts_kernel() {
    int i = blockIdx.x * blockDim.x + threadIdx.x;
    if (i < NN) g_counts[i] = 0;
}

__global__ void hist_kernel(const int* __restrict__ dst) {
    int e = blockIdx.x * blockDim.x + threadIdx.x;
    if (e < EE) atomicAdd(&g_counts[dst[e]], 1);
}

__global__ __launch_bounds__(SCAN_B) void scanA_kernel() {
    __shared__ int sh[SCAN_B];
    int i = blockIdx.x * SCAN_B + threadIdx.x;
    int v = (i < NN) ? g_counts[i] : 0;
    sh[threadIdx.x] = v;
    __syncthreads();
    #pragma unroll
    for (int off = 1; off < SCAN_B; off <<= 1) {
        int t = (threadIdx.x >= off) ? sh[threadIdx.x - off] : 0;
        __syncthreads();
        sh[threadIdx.x] += t;
        __syncthreads();
    }
    if (i < NN) g_rowptr[i] = sh[threadIdx.x] - v;
    if (threadIdx.x == SCAN_B - 1) g_bsum[blockIdx.x] = sh[SCAN_B - 1];
}

__global__ __launch_bounds__(128) void scanB_kernel() {
    __shared__ int wsum[4];
    int t = threadIdx.x;
    int lane = t & 31, wid = t >> 5;
    int v = (t < NBLK) ? g_bsum[t] : 0;
    int x = v;
    #pragma unroll
    for (int off = 1; off < 32; off <<= 1) {
        int y = __shfl_up_sync(0xffffffffu, x, off);
        if (lane >= off) x += y;
    }
    if (lane == 31) wsum[wid] = x;
    __syncthreads();
    int add = 0;
    #pragma unroll
    for (int wq = 0; wq < 4; wq++) if (wq < wid) add += wsum[wq];
    if (t < NBLK) g_bsum[t] = x + add - v;
}

__global__ void scanC_kernel() {
    int i = blockIdx.x * blockDim.x + threadIdx.x;
    if (i < NN) {
        int r = g_rowptr[i] + g_bsum[i / SCAN_B];
        g_rowptr[i] = r;
        g_cursor[i] = r;
    }
    if (i == 0) g_rowptr[NN] = EE;
}

__global__ void fill_kernel(const int* __restrict__ src, const int* __restrict__ dst) {
    int e = blockIdx.x * blockDim.x + threadIdx.x;
    if (e < EE) {
        int p = atomicAdd(&g_cursor[dst[e]], 1);
        g_colidx[p] = src[e];
    }
}

// ---------------- GEMM1: 3xBF16 split on m16n8k16 tensor cores --------------
// feat1[N,256] = x[N,256] @ W1[256,256]; block 128x128, BK=32, 8 warps.
// hi/lo bf16 planes in SMEM (packed 2 per u32 along k) -> same footprint as fp32,
// BK stays 32; mainloop = LDS + mma only. C += Ahi*Bhi + Ahi*Blo + Alo*Bhi.
__device__ __forceinline__ void bf16split2(float e0, float e1, uint32_t& hp, uint32_t& lp) {
    // hp = {hi16: bf16(e1), lo16: bf16(e0)}  (e0 = lower-k element)
    asm("cvt.rn.bf16x2.f32 %0, %1, %2;" : "=r"(hp) : "f"(e1), "f"(e0));
    float h0 = __uint_as_float(hp << 16);
    float h1 = __uint_as_float(hp & 0xFFFF0000u);
    asm("cvt.rn.bf16x2.f32 %0, %1, %2;" : "=r"(lp) : "f"(e1 - h1), "f"(e0 - h0));
}

__device__ __forceinline__ void mma_bf16(float* c, const uint32_t* a, const uint32_t* b) {
    asm volatile(
        "mma.sync.aligned.m16n8k16.row.col.f32.bf16.bf16.f32 "
        "{%0,%1,%2,%3}, {%4,%5,%6,%7}, {%8,%9}, {%0,%1,%2,%3};"
        : "+f"(c[0]), "+f"(c[1]), "+f"(c[2]), "+f"(c[3])
        : "r"(a[0]), "r"(a[1]), "r"(a[2]), "r"(a[3]), "r"(b[0]), "r"(b[1]));
}

__global__ __launch_bounds__(256) void gemm1_tc_kernel(const float* __restrict__ A,
                                                       const float* __restrict__ B) {
    // planes: [kpair][col], kpair = k/2 (16 pairs for BK=32); pad 136 (8-bank row offset)
    __shared__ uint32_t AsH[16][136], AsL[16][136];
    __shared__ uint32_t BsH[16][136], BsL[16][136];
    int tid = threadIdx.x;
    int lane = tid & 31, wid = tid >> 5;
    int g = lane >> 2, t4 = lane & 3;
    int row0 = blockIdx.x * 128, col0 = blockIdx.y * 128;
    int wm = (wid & 1) * 64, wn = (wid >> 1) * 32;

    float c[4][4][4];
    #pragma unroll
    for (int mt = 0; mt < 4; mt++)
        #pragma unroll
        for (int nt = 0; nt < 4; nt++)
            #pragma unroll
            for (int q = 0; q < 4; q++) c[mt][nt][q] = 0.f;

    int am = tid >> 1;              // A row in tile (0..127)
    int akh = (tid & 1) * 16;       // A k half: 0 or 16
    int bn = (tid & 31) * 4;        // B col (0..124)
    int bkp0 = tid >> 5;            // B kpair base (0..7)

    for (int k0 = 0; k0 < FDIM; k0 += 32) {
        // A producer: row am, k [akh, akh+16); pairs along k
        {
            int r = row0 + am;
            #pragma unroll
            for (int q = 0; q < 4; q++) {
                int kk = akh + q * 4;           // even
                float4 v = make_float4(0.f, 0.f, 0.f, 0.f);
                if (r < NN) v = *(const float4*)&A[(size_t)r * FDIM + k0 + kk];
                uint32_t h01, l01, h23, l23;
                bf16split2(v.x, v.y, h01, l01);
                bf16split2(v.z, v.w, h23, l23);
                int kp = kk >> 1;
                AsH[kp][am] = h01; AsL[kp][am] = l01;
                AsH[kp + 1][am] = h23; AsL[kp + 1][am] = l23;
            }
        }
        // B producer: kpair kp, cols bn..bn+3; pairs along k (two row loads)
        #pragma unroll
        for (int q = 0; q < 2; q++) {
            int kp = bkp0 + q * 8;              // 0..15
            int krow = k0 + 2 * kp;
            float4 u0 = *(const float4*)&B[(size_t)krow * 256 + col0 + bn];
            float4 u1 = *(const float4*)&B[(size_t)(krow + 1) * 256 + col0 + bn];
            uint32_t h[4], l[4];
            bf16split2(u0.x, u1.x, h[0], l[0]);
            bf16split2(u0.y, u1.y, h[1], l[1]);
            bf16split2(u0.z, u1.z, h[2], l[2]);
            bf16split2(u0.w, u1.w, h[3], l[3]);
            *(uint4*)&BsH[kp][bn] = make_uint4(h[0], h[1], h[2], h[3]);
            *(uint4*)&BsL[kp][bn] = make_uint4(l[0], l[1], l[2], l[3]);
        }
        __syncthreads();

        #pragma unroll
        for (int ks = 0; ks < 2; ks++) {        // two k16 steps per BK=32
            int kb = ks * 8;                    // kpair offset
            uint32_t ahi[4][4], alo[4][4];
            #pragma unroll
            for (int mt = 0; mt < 4; mt++) {
                int mr = wm + mt * 16;
                ahi[mt][0] = AsH[kb + t4][mr + g];
                ahi[mt][1] = AsH[kb + t4][mr + g + 8];
                ahi[mt][2] = AsH[kb + t4 + 4][mr + g];
                ahi[mt][3] = AsH[kb + t4 + 4][mr + g + 8];
                alo[mt][0] = AsL[kb + t4][mr + g];
                alo[mt][1] = AsL[kb + t4][mr + g + 8];
                alo[mt][2] = AsL[kb + t4 + 4][mr + g];
                alo[mt][3] = AsL[kb + t4 + 4][mr + g + 8];
            }
            uint32_t bhi[4][2], blo[4][2];
            #pragma unroll
            for (int nt = 0; nt < 4; nt++) {
                int nc = wn + nt * 8 + g;
                bhi[nt][0] = BsH[kb + t4][nc];
                bhi[nt][1] = BsH[kb + t4 + 4][nc];
                blo[nt][0] = BsL[kb + t4][nc];
                blo[nt][1] = BsL[kb + t4 + 4][nc];
            }
            #pragma unroll
            for (int mt = 0; mt < 4; mt++)
                #pragma unroll
                for (int nt = 0; nt < 4; nt++) {
                    mma_bf16(c[mt][nt], ahi[mt], bhi[nt]);
                    mma_bf16(c[mt][nt], ahi[mt], blo[nt]);
                    mma_bf16(c[mt][nt], alo[mt], bhi[nt]);
                }
        }
        __syncthreads();
    }

    // epilogue: write PERMUTED columns
    #pragma unroll
    for (int mt = 0; mt < 4; mt++) {
        int r = row0 + wm + mt * 16 + g;
        #pragma unroll
        for (int nt = 0; nt < 4; nt++) {
            int cc = col0 + wn + nt * 8 + 2 * t4;
            int nc = permcol(cc);
            if (r < NN)
                *(float2*)&g_feat1[(size_t)r * FDIM + nc] = make_float2(c[mt][nt][0], c[mt][nt][1]);
            if (r + 8 < NN)
                *(float2*)&g_feat1[(size_t)(r + 8) * FDIM + nc] = make_float2(c[mt][nt][2], c[mt][nt][3]);
        }
    }
}

// ---------------- layer-1 fused edge-softmax + aggregate --------------------
__device__ __forceinline__ float4 leaky4(float4 v) {
    float4 r;
    r.x = v.x > 0.f ? v.x : NEG_SLOPE * v.x;
    r.y = v.y > 0.f ? v.y : NEG_SLOPE * v.y;
    r.z = v.z > 0.f ? v.z : NEG_SLOPE * v.z;
    r.w = v.w > 0.f ? v.w : NEG_SLOPE * v.w;
    return r;
}
__device__ __forceinline__ float eluf(float x) { return x > 0.f ? x : expm1f(x); }
__device__ __forceinline__ float dot4(float4 a, float4 b) {
    return a.x * b.x + a.y * b.y + a.z * b.z + a.w * b.w;
}
__device__ __forceinline__ float4 add4(float4 a, float4 b) {
    return make_float4(a.x + b.x, a.y + b.y, a.z + b.z, a.w + b.w);
}

__global__ __launch_bounds__(256) void agg1_kernel(const float* __restrict__ attn) {
    int w = (blockIdx.x * blockDim.x + threadIdx.x) >> 5;   // < NN by grid sizing
    int lane = threadIdx.x & 31;

    const float4* feat = (const float4*)g_feat1;   // permuted, 64 float4/row
    const float4* at4  = (const float4*)attn;      // orig layout

    int hh = lane >> 3, jj = lane & 7;
    float4 aA = at4[16 * hh + jj];
    float4 aB = at4[16 * hh + 8 + jj];
    float4 fd0 = feat[(size_t)w * 64 + lane];
    float4 fd1 = feat[(size_t)w * 64 + 32 + lane];

    int beg = g_rowptr[w], end = g_rowptr[w + 1];
    float m = -CUDART_INF_F, d = 0.f;
    float4 acc0 = make_float4(0.f, 0.f, 0.f, 0.f);
    float4 acc1 = make_float4(0.f, 0.f, 0.f, 0.f);

    int k = beg;
    for (; k + 1 < end; k += 2) {
        int sa = g_colidx[k];
        int sb = g_colidx[k + 1];
        float4 va0 = feat[(size_t)sa * 64 + lane];
        float4 va1 = feat[(size_t)sa * 64 + 32 + lane];
        float4 vb0 = feat[(size_t)sb * 64 + lane];
        float4 vb1 = feat[(size_t)sb * 64 + 32 + lane];
        float pa = dot4(leaky4(add4(va0, fd0)), aA) + dot4(leaky4(add4(va1, fd1)), aB);
        float pb = dot4(leaky4(add4(vb0, fd0)), aA) + dot4(leaky4(add4(vb1, fd1)), aB);
        #pragma unroll
        for (int off = 4; off > 0; off >>= 1) {
            pa += __shfl_xor_sync(0xffffffffu, pa, off);
            pb += __shfl_xor_sync(0xffffffffu, pb, off);
        }
        {
            float nm = fmaxf(m, pa);
            float sc = __expf(m - nm);
            float ex = __expf(pa - nm);
            d = d * sc + ex;
            acc0.x = acc0.x * sc + ex * va0.x; acc0.y = acc0.y * sc + ex * va0.y;
            acc0.z = acc0.z * sc + ex * va0.z; acc0.w = acc0.w * sc + ex * va0.w;
            acc1.x = acc1.x * sc + ex * va1.x; acc1.y = acc1.y * sc + ex * va1.y;
            acc1.z = acc1.z * sc + ex * va1.z; acc1.w = acc1.w * sc + ex * va1.w;
            m = nm;
        }
        {
            float nm = fmaxf(m, pb);
            float sc = __expf(m - nm);
            float ex = __expf(pb - nm);
            d = d * sc + ex;
            acc0.x = acc0.x * sc + ex * vb0.x; acc0.y = acc0.y * sc + ex * vb0.y;
            acc0.z = acc0.z * sc + ex * vb0.z; acc0.w = acc0.w * sc + ex * vb0.w;
            acc1.x = acc1.x * sc + ex * vb1.x; acc1.y = acc1.y * sc + ex * vb1.y;
            acc1.z = acc1.z * sc + ex * vb1.z; acc1.w = acc1.w * sc + ex * vb1.w;
            m = nm;
        }
    }
    if (k < end) {
        int s = g_colidx[k];
        float4 v0 = feat[(size_t)s * 64 + lane];
        float4 v1 = feat[(size_t)s * 64 + 32 + lane];
        float p = dot4(leaky4(add4(v0, fd0)), aA) + dot4(leaky4(add4(v1, fd1)), aB);
        #pragma unroll
        for (int off = 4; off > 0; off >>= 1) p += __shfl_xor_sync(0xffffffffu, p, off);
        float nm = fmaxf(m, p);
        float sc = __expf(m - nm);
        float ex = __expf(p - nm);
        d = d * sc + ex;
        acc0.x = acc0.x * sc + ex * v0.x; acc0.y = acc0.y * sc + ex * v0.y;
        acc0.z = acc0.z * sc + ex * v0.z; acc0.w = acc0.w * sc + ex * v0.w;
        acc1.x = acc1.x * sc + ex * v1.x; acc1.y = acc1.y * sc + ex * v1.y;
        acc1.z = acc1.z * sc + ex * v1.z; acc1.w = acc1.w * sc + ex * v1.w;
    }

    float inv = d > 0.f ? 1.f / d : 0.f;
    float4 o0 = make_float4(eluf(acc0.x * inv), eluf(acc0.y * inv), eluf(acc0.z * inv), eluf(acc0.w * inv));
    float4 o1 = make_float4(eluf(acc1.x * inv), eluf(acc1.y * inv), eluf(acc1.z * inv), eluf(acc1.w * inv));
    float4* out = (float4*)g_h2;
    out[(size_t)w * 64 + lane] = o0;
    out[(size_t)w * 64 + 32 + lane] = o1;
}

// ---------------- GEMM2: feat2[N,40] = h2[N,256] @ W2[256,40] ---------------
__global__ __launch_bounds__(256) void gemm2_kernel(const float* __restrict__ W2) {
    __shared__ float hs[4][256];
    int n0 = blockIdx.x * 4;
    int tid = threadIdx.y * 64 + threadIdx.x;
    for (int i = tid; i < 1024; i += 256) {
        int r = n0 + (i >> 8);
        int pc = i & 255;
        float v = (r < NN) ? g_h2[(size_t)r * 256 + pc] : 0.f;
        hs[i >> 8][invcol(pc)] = v;
    }
    __syncthreads();
    int c = threadIdx.x;
    int r = n0 + threadIdx.y;
    if (c < F2DIM && r < NN) {
        float s = 0.f;
        #pragma unroll 8
        for (int k = 0; k < 256; k++) s += hs[threadIdx.y][k] * W2[k * F2DIM + c];
        G_FEAT2[(size_t)r * F2DIM + c] = s;
    }
}

// ---------------- layer-2 fused edge-softmax + aggregate --------------------
__global__ __launch_bounds__(256) void agg2_kernel(const float* __restrict__ attn2,
                                                   float* __restrict__ out) {
    int w = (blockIdx.x * blockDim.x + threadIdx.x) >> 5;
    int lane = threadIdx.x & 31;

    bool hi = lane < 8;
    float a_lo = attn2[lane];
    float a_hi = hi ? attn2[32 + lane] : 0.f;
    float fd_lo = G_FEAT2[(size_t)w * F2DIM + lane];
    float fd_hi = hi ? G_FEAT2[(size_t)w * F2DIM + 32 + lane] : 0.f;

    int beg = g_rowptr[w], end = g_rowptr[w + 1];
    float m = -CUDART_INF_F, d = 0.f, acc_lo = 0.f, acc_hi = 0.f;

    for (int k = beg; k < end; k++) {
        int s = g_colidx[k];
        float v_lo = G_FEAT2[(size_t)s * F2DIM + lane];
        float v_hi = hi ? G_FEAT2[(size_t)s * F2DIM + 32 + lane] : 0.f;
        float e_lo = v_lo + fd_lo; e_lo = e_lo > 0.f ? e_lo : NEG_SLOPE * e_lo;
        float e_hi = v_hi + fd_hi; e_hi = e_hi > 0.f ? e_hi : NEG_SLOPE * e_hi;
        float p = e_lo * a_lo + e_hi * a_hi;
        #pragma unroll
        for (int off = 16; off > 0; off >>= 1) p += __shfl_xor_sync(0xffffffffu, p, off);
        float nm = fmaxf(m, p);
        float sc = __expf(m - nm);
        float ex = __expf(p - nm);
        d = d * sc + ex;
        acc_lo = acc_lo * sc + ex * v_lo;
        acc_hi = acc_hi * sc + ex * v_hi;
        m = nm;
    }

    float inv = d > 0.f ? 1.f / d : 0.f;
    out[(size_t)w * F2DIM + lane] = acc_lo * inv;
    if (hi) out[(size_t)w * F2DIM + 32 + lane] = acc_hi * inv;
}

// ---------------- launch ----------------------------------------------------
extern "C" void kernel_launch(void* const* d_in, const int* in_sizes, int n_in,
                              void* d_out, int out_size) {
    const float* x     = (const float*)d_in[0];
    const int*   src   = (const int*)d_in[1];
    const int*   dst   = (const int*)d_in[2];
    const float* W1    = (const float*)d_in[3];
    const float* attn1 = (const float*)d_in[4];
    const float* W2    = (const float*)d_in[5];
    const float* attn2 = (const float*)d_in[6];
    float* out = (float*)d_out;

    zero_counts_kernel<<<(NN + 255) / 256, 256>>>();
    hist_kernel<<<(EE + 255) / 256, 256>>>(dst);
    scanA_kernel<<<NBLK, SCAN_B>>>();
    scanB_kernel<<<1, 128>>>();
    scanC_kernel<<<(NN + 255) / 256, 256>>>();
    fill_kernel<<<(EE + 255) / 256, 256>>>(src, dst);

    gemm1_tc_kernel<<<dim3((NN + 127) / 128, 2), 256>>>(x, W1);
    agg1_kernel<<<(NN * 32) / 256, 256>>>(attn1);

    gemm2_kernel<<<(NN + 3) / 4, dim3(64, 4)>>>(W2);
    agg2_kernel<<<(NN * 32) / 256, 256>>>(attn2, out);
}